// round 4
// baseline (speedup 1.0000x reference)
#include <cuda_runtime.h>

#define NN 100000
#define NE 1600000
#define NG 512
#define F_IN 128
#define F_H1 128
#define F_H2 256
#define N_GROUPS 16
#define N_FAM 10

// ---------------- scratch (device globals: allocation-guard-safe) ----------------
__device__ float g_xw1[(size_t)NN * F_H1];   // x @ W1
__device__ float g_agg1[(size_t)NN * F_H1];  // layer-1 aggregation (pre-relu)
__device__ float g_xw2[(size_t)NN * F_H2];   // relu(h1) @ W2
__device__ float g_agg2[(size_t)NN * F_H2];  // layer-2 aggregation (= h)
__device__ float g_dinv[NN];                 // rsqrt(deg+1)
__device__ float g_coef[NE];                 // dinv[src]*dinv[dst]
__device__ float g_pool[NG * F_H2];          // segment sums
__device__ float g_cnt[NG];                  // segment counts

// ---------------- degree / normalization ----------------
__global__ void zero_deg_kernel() {
    int i = blockIdx.x * blockDim.x + threadIdx.x;
    if (i < NN) g_dinv[i] = 0.f;
}

__global__ void deg_kernel(const int* __restrict__ dst) {
    int e = blockIdx.x * blockDim.x + threadIdx.x;
    if (e < NE) atomicAdd(&g_dinv[dst[e]], 1.0f);
}

__global__ void dinv_kernel() {
    int i = blockIdx.x * blockDim.x + threadIdx.x;
    if (i < NN) g_dinv[i] = rsqrtf(g_dinv[i] + 1.0f);
}

__global__ void coef_kernel(const int* __restrict__ src, const int* __restrict__ dst) {
    int e = blockIdx.x * blockDim.x + threadIdx.x;
    if (e < NE) g_coef[e] = g_dinv[src[e]] * g_dinv[dst[e]];
}

// ---------------- GEMM: C[M,N] = op(A)[M,K] @ B[K,N] ----------------
#define GBM 64
#define GBN 64
#define GBK 32
__global__ void gemm_kernel(const float* __restrict__ A, const float* __restrict__ B,
                            float* __restrict__ C, int M, int N, int K, int relu_a) {
    __shared__ float As[GBK][GBM + 4];
    __shared__ float Bs[GBK][GBN + 4];
    int tid = threadIdx.x;            // 256 threads
    int bm = blockIdx.x * GBM;
    int bn = blockIdx.y * GBN;
    int trow = (tid >> 4) * 4;        // 16x16 thread grid, 4x4 micro-tile
    int tcol = (tid & 15) * 4;
    float acc[4][4];
#pragma unroll
    for (int i = 0; i < 4; i++)
#pragma unroll
        for (int j = 0; j < 4; j++) acc[i][j] = 0.f;

    for (int k0 = 0; k0 < K; k0 += GBK) {
        // A tile: GBM x GBK, consecutive threads read consecutive k (coalesced)
        for (int i = tid; i < GBM * GBK; i += 256) {
            int m = i >> 5, k = i & 31;
            int gm = bm + m;
            float v = (gm < M) ? A[(size_t)gm * K + k0 + k] : 0.f;
            if (relu_a) v = fmaxf(v, 0.f);
            As[k][m] = v;
        }
        // B tile: GBK x GBN
        for (int i = tid; i < GBK * GBN; i += 256) {
            int k = i >> 6, n = i & 63;
            Bs[k][n] = B[(size_t)(k0 + k) * N + bn + n];
        }
        __syncthreads();
#pragma unroll
        for (int k = 0; k < GBK; k++) {
            float a[4], b[4];
#pragma unroll
            for (int i = 0; i < 4; i++) a[i] = As[k][trow + i];
#pragma unroll
            for (int j = 0; j < 4; j++) b[j] = Bs[k][tcol + j];
#pragma unroll
            for (int i = 0; i < 4; i++)
#pragma unroll
                for (int j = 0; j < 4; j++) acc[i][j] += a[i] * b[j];
        }
        __syncthreads();
    }
#pragma unroll
    for (int i = 0; i < 4; i++) {
        int gm = bm + trow + i;
        if (gm < M) {
#pragma unroll
            for (int j = 0; j < 4; j++)
                C[(size_t)gm * N + bn + tcol + j] = acc[i][j];
        }
    }
}

// ---------------- init agg = xw * dinv^2 + bias ----------------
template <int F>
__global__ void init_agg_kernel(const float* __restrict__ xw, const float* __restrict__ bias,
                                float* __restrict__ agg) {
    const int F4 = F / 4;
    int i = blockIdx.x * blockDim.x + threadIdx.x;   // over NN*F4 float4s
    if (i >= NN * F4) return;
    int node = i / F4;
    int f4 = i - node * F4;
    float d = g_dinv[node];
    float dd = d * d;
    float4 v = ((const float4*)xw)[i];
    float4 b = ((const float4*)bias)[f4];
    float4 o;
    o.x = fmaf(v.x, dd, b.x);
    o.y = fmaf(v.y, dd, b.y);
    o.z = fmaf(v.z, dd, b.z);
    o.w = fmaf(v.w, dd, b.w);
    ((float4*)agg)[i] = o;
}

// ---------------- edge scatter: agg[dst] += xw[src] * coef (warp per edge) ----------------
template <int F>
__global__ void scatter_kernel(const float* __restrict__ xw, const int* __restrict__ srcv,
                               const int* __restrict__ dstv, float* __restrict__ agg) {
    int e = (blockIdx.x * blockDim.x + threadIdx.x) >> 5;
    if (e >= NE) return;
    int lane = threadIdx.x & 31;
    int src = srcv[e];
    int dst = dstv[e];
    float c = g_coef[e];
    const float4* srow = (const float4*)(xw + (size_t)src * F);
    float* drow = agg + (size_t)dst * F;
#pragma unroll
    for (int i = lane; i < F / 4; i += 32) {
        float4 v = srow[i];
        float* p = drow + i * 4;
        atomicAdd(p + 0, v.x * c);
        atomicAdd(p + 1, v.y * c);
        atomicAdd(p + 2, v.z * c);
        atomicAdd(p + 3, v.w * c);
    }
}

// ---------------- pooling ----------------
__global__ void zero_pool_kernel() {
    int i = blockIdx.x * blockDim.x + threadIdx.x;
    if (i < NG * F_H2) g_pool[i] = 0.f;
    if (i < NG) g_cnt[i] = 0.f;
}

__global__ void pool_kernel(const int* __restrict__ batch) {
    int node = (blockIdx.x * blockDim.x + threadIdx.x) >> 5;
    if (node >= NN) return;
    int lane = threadIdx.x & 31;
    int g = batch[node];
    const float4* row = (const float4*)(g_agg2 + (size_t)node * F_H2);
    float* drow = g_pool + g * F_H2;
#pragma unroll
    for (int i = lane; i < F_H2 / 4; i += 32) {
        float4 v = row[i];
        float* p = drow + i * 4;
        atomicAdd(p + 0, v.x);
        atomicAdd(p + 1, v.y);
        atomicAdd(p + 2, v.z);
        atomicAdd(p + 3, v.w);
    }
    if (lane == 0) atomicAdd(&g_cnt[g], 1.0f);
}

// ---------------- heads: group + family logits ----------------
__global__ void logits_kernel(const float* __restrict__ Wg, const float* __restrict__ bg,
                              const float* __restrict__ Wf, const float* __restrict__ bf,
                              float* __restrict__ out) {
    __shared__ float p[F_H2];
    int b = blockIdx.x;       // graph
    int t = threadIdx.x;      // 256
    float cnt = fmaxf(g_cnt[b], 1.0f);
    p[t] = g_pool[b * F_H2 + t] / cnt;
    __syncthreads();

    if (t < N_GROUPS) {
        float s = bg[t];
#pragma unroll 8
        for (int k = 0; k < F_H2; k++) s = fmaf(p[k], Wg[k * N_GROUPS + t], s);
        out[b * N_GROUPS + t] = s;
    }
    if (t < N_GROUPS * N_FAM) {
        int g = t / N_FAM, f = t - g * N_FAM;
        float s = bf[g * N_FAM + f];
        const float* w = Wf + (size_t)g * F_H2 * N_FAM + f;
#pragma unroll 8
        for (int k = 0; k < F_H2; k++) s = fmaf(p[k], w[k * N_FAM], s);
        out[NG * N_GROUPS + (size_t)g * NG * N_FAM + b * N_FAM + f] = s;
    }
}

// ---------------- launcher ----------------
extern "C" void kernel_launch(void* const* d_in, const int* in_sizes, int n_in,
                              void* d_out, int out_size) {
    const float* x     = (const float*)d_in[0];
    const int*   ei    = (const int*)d_in[1];     // [2, NE] int32 (harness downcasts int64)
    const int*   batch = (const int*)d_in[2];
    const float* W1    = (const float*)d_in[3];
    const float* b1    = (const float*)d_in[4];
    const float* W2    = (const float*)d_in[5];
    const float* b2    = (const float*)d_in[6];
    const float* Wg    = (const float*)d_in[7];
    const float* bg    = (const float*)d_in[8];
    const float* Wf    = (const float*)d_in[9];
    const float* bf    = (const float*)d_in[10];
    float* out = (float*)d_out;

    const int* src = ei;
    const int* dst = ei + NE;

    float *xw1, *agg1, *xw2, *agg2;
    cudaGetSymbolAddress((void**)&xw1,  g_xw1);
    cudaGetSymbolAddress((void**)&agg1, g_agg1);
    cudaGetSymbolAddress((void**)&xw2,  g_xw2);
    cudaGetSymbolAddress((void**)&agg2, g_agg2);

    // normalization coefficients
    zero_deg_kernel<<<(NN + 255) / 256, 256>>>();
    deg_kernel<<<(NE + 255) / 256, 256>>>(dst);
    dinv_kernel<<<(NN + 255) / 256, 256>>>();
    coef_kernel<<<(NE + 255) / 256, 256>>>(src, dst);

    // layer 1: xw1 = x @ W1 ; agg1 = self + bias ; scatter
    gemm_kernel<<<dim3((NN + GBM - 1) / GBM, F_H1 / GBN), 256>>>(x, W1, xw1, NN, F_H1, F_IN, 0);
    init_agg_kernel<F_H1><<<(NN * (F_H1 / 4) + 255) / 256, 256>>>(xw1, b1, agg1);
    scatter_kernel<F_H1><<<(NE * 32 + 255) / 256, 256>>>(xw1, src, dst, agg1);

    // layer 2: xw2 = relu(agg1) @ W2 (relu fused into A-load) ; agg2 ; scatter
    gemm_kernel<<<dim3((NN + GBM - 1) / GBM, F_H2 / GBN), 256>>>(agg1, W2, xw2, NN, F_H2, F_H1, 1);
    init_agg_kernel<F_H2><<<(NN * (F_H2 / 4) + 255) / 256, 256>>>(xw2, b2, agg2);
    scatter_kernel<F_H2><<<(NE * 32 + 255) / 256, 256>>>(xw2, src, dst, agg2);

    // pooling + heads
    zero_pool_kernel<<<(NG * F_H2 + 255) / 256, 256>>>();
    pool_kernel<<<(NN * 32 + 255) / 256, 256>>>(batch);
    logits_kernel<<<NG, F_H2>>>(Wg, bg, Wf, bf, out);
}

// round 5
// speedup vs baseline: 2.9388x; 2.9388x over previous
#include <cuda_runtime.h>

#define NN 100000
#define NE 1600000
#define NG 512
#define F_IN 128
#define F_H1 128
#define F_H2 256
#define N_GROUPS 16
#define N_FAM 10

#define SCAN_BLK 256
#define NBLK_SCAN ((NN + SCAN_BLK - 1) / SCAN_BLK)   // 391

// ---------------- scratch (device globals: allocation-guard-safe) ----------------
__device__ float g_xw1[(size_t)NN * F_H1];   // x @ W1
__device__ float g_agg1[(size_t)NN * F_H1];  // layer-1 aggregation (pre-relu)
__device__ float g_xw2[(size_t)NN * F_H2];   // relu(agg1) @ W2
__device__ float g_dinv[NN];                 // rsqrt(deg+1)
__device__ int   g_deg[NN];                  // in-degree histogram
__device__ int   g_rowptr[NN + 1];           // CSR row pointers (by dst)
__device__ int   g_fill[NN];                 // running fill cursors
__device__ int   g_blocksum[NBLK_SCAN + 1];  // scan partials
__device__ int   g_csr_src[NE];              // src ids, dst-ordered
__device__ float g_csr_coef[NE];             // edge coefficients, dst-ordered
__device__ float g_pool[NG * F_H2];          // segment sums
__device__ float g_cnt[NG];                  // segment counts

// ---------------- degree histogram + normalization ----------------
__global__ void zero_kernel() {
    int i = blockIdx.x * blockDim.x + threadIdx.x;
    if (i < NN) g_deg[i] = 0;
    if (i < NG * F_H2) g_pool[i] = 0.f;
    if (i < NG) g_cnt[i] = 0.f;
}

__global__ void hist_kernel(const int* __restrict__ dst) {
    int e = blockIdx.x * blockDim.x + threadIdx.x;
    if (e < NE) atomicAdd(&g_deg[dst[e]], 1);
}

__global__ void dinv_kernel() {
    int i = blockIdx.x * blockDim.x + threadIdx.x;
    if (i < NN) g_dinv[i] = rsqrtf((float)g_deg[i] + 1.0f);
}

// ---------------- exclusive scan of g_deg -> g_rowptr ----------------
__global__ void scan_block_kernel() {
    __shared__ int s[SCAN_BLK];
    int tid = threadIdx.x;
    int i = blockIdx.x * SCAN_BLK + tid;
    int v = (i < NN) ? g_deg[i] : 0;
    s[tid] = v;
    __syncthreads();
#pragma unroll
    for (int off = 1; off < SCAN_BLK; off <<= 1) {
        int t = (tid >= off) ? s[tid - off] : 0;
        __syncthreads();
        s[tid] += t;
        __syncthreads();
    }
    if (i < NN) g_rowptr[i] = s[tid] - v;      // exclusive within block
    if (tid == SCAN_BLK - 1) g_blocksum[blockIdx.x] = s[tid];
}

__global__ void scan_sums_kernel() {
    __shared__ int s[512];
    int tid = threadIdx.x;                      // 512 threads
    int v = (tid < NBLK_SCAN) ? g_blocksum[tid] : 0;
    s[tid] = v;
    __syncthreads();
#pragma unroll
    for (int off = 1; off < 512; off <<= 1) {
        int t = (tid >= off) ? s[tid - off] : 0;
        __syncthreads();
        s[tid] += t;
        __syncthreads();
    }
    if (tid < NBLK_SCAN) g_blocksum[tid] = s[tid] - v;   // exclusive
}

__global__ void scan_add_kernel() {
    int i = blockIdx.x * blockDim.x + threadIdx.x;
    if (i < NN) {
        int r = g_rowptr[i] + g_blocksum[i / SCAN_BLK];
        g_rowptr[i] = r;
        g_fill[i] = r;
    }
    if (i == 0) g_rowptr[NN] = NE;
}

// ---------------- CSR fill (dst-ordered src + coef) ----------------
__global__ void csr_fill_kernel(const int* __restrict__ src, const int* __restrict__ dst) {
    int e = blockIdx.x * blockDim.x + threadIdx.x;
    if (e >= NE) return;
    int s = src[e], d = dst[e];
    int pos = atomicAdd(&g_fill[d], 1);
    g_csr_src[pos] = s;
    g_csr_coef[pos] = g_dinv[s] * g_dinv[d];
}

// ---------------- GEMM: C[M,N] = op(A)[M,K] @ B[K,N] ----------------
#define GBM 64
#define GBN 64
#define GBK 32
__global__ void gemm_kernel(const float* __restrict__ A, const float* __restrict__ B,
                            float* __restrict__ C, int M, int N, int K, int relu_a) {
    __shared__ float As[GBK][GBM + 4];
    __shared__ float Bs[GBK][GBN + 4];
    int tid = threadIdx.x;            // 256 threads
    int bm = blockIdx.x * GBM;
    int bn = blockIdx.y * GBN;
    int trow = (tid >> 4) * 4;        // 16x16 thread grid, 4x4 micro-tile
    int tcol = (tid & 15) * 4;
    float acc[4][4];
#pragma unroll
    for (int i = 0; i < 4; i++)
#pragma unroll
        for (int j = 0; j < 4; j++) acc[i][j] = 0.f;

    for (int k0 = 0; k0 < K; k0 += GBK) {
        for (int i = tid; i < GBM * GBK; i += 256) {
            int m = i >> 5, k = i & 31;
            int gm = bm + m;
            float v = (gm < M) ? A[(size_t)gm * K + k0 + k] : 0.f;
            if (relu_a) v = fmaxf(v, 0.f);
            As[k][m] = v;
        }
        for (int i = tid; i < GBK * GBN; i += 256) {
            int k = i >> 6, n = i & 63;
            Bs[k][n] = B[(size_t)(k0 + k) * N + bn + n];
        }
        __syncthreads();
#pragma unroll
        for (int k = 0; k < GBK; k++) {
            float a[4], b[4];
#pragma unroll
            for (int i = 0; i < 4; i++) a[i] = As[k][trow + i];
#pragma unroll
            for (int j = 0; j < 4; j++) b[j] = Bs[k][tcol + j];
#pragma unroll
            for (int i = 0; i < 4; i++)
#pragma unroll
                for (int j = 0; j < 4; j++) acc[i][j] += a[i] * b[j];
        }
        __syncthreads();
    }
#pragma unroll
    for (int i = 0; i < 4; i++) {
        int gm = bm + trow + i;
        if (gm < M) {
#pragma unroll
            for (int j = 0; j < 4; j++)
                C[(size_t)gm * N + bn + tcol + j] = acc[i][j];
        }
    }
}

// ---------------- layer-1 gather: agg1[n] = sum_in xw1[src]*coef + xw1[n]*dinv^2 + b1 ----------------
// warp per node; F=128 -> one float4 per lane
__global__ void gather1_kernel(const float* __restrict__ b1) {
    int n = (blockIdx.x * blockDim.x + threadIdx.x) >> 5;
    if (n >= NN) return;
    int lane = threadIdx.x & 31;
    int e = g_rowptr[n];
    int end = g_rowptr[n + 1];
    float4 acc = make_float4(0.f, 0.f, 0.f, 0.f);
    for (; e + 1 < end; e += 2) {
        int s0 = g_csr_src[e];     float c0 = g_csr_coef[e];
        int s1 = g_csr_src[e + 1]; float c1 = g_csr_coef[e + 1];
        float4 v0 = ((const float4*)(g_xw1 + (size_t)s0 * F_H1))[lane];
        float4 v1 = ((const float4*)(g_xw1 + (size_t)s1 * F_H1))[lane];
        acc.x += v0.x * c0 + v1.x * c1;
        acc.y += v0.y * c0 + v1.y * c1;
        acc.z += v0.z * c0 + v1.z * c1;
        acc.w += v0.w * c0 + v1.w * c1;
    }
    if (e < end) {
        int s0 = g_csr_src[e]; float c0 = g_csr_coef[e];
        float4 v0 = ((const float4*)(g_xw1 + (size_t)s0 * F_H1))[lane];
        acc.x += v0.x * c0; acc.y += v0.y * c0; acc.z += v0.z * c0; acc.w += v0.w * c0;
    }
    float d = g_dinv[n];
    float dd = d * d;
    float4 self = ((const float4*)(g_xw1 + (size_t)n * F_H1))[lane];
    float4 bb = ((const float4*)b1)[lane];
    float4 o;
    o.x = acc.x + fmaf(self.x, dd, bb.x);
    o.y = acc.y + fmaf(self.y, dd, bb.y);
    o.z = acc.z + fmaf(self.z, dd, bb.z);
    o.w = acc.w + fmaf(self.w, dd, bb.w);
    ((float4*)(g_agg1 + (size_t)n * F_H1))[lane] = o;
}

// ---------------- layer-2 gather + fused pooling ----------------
// warp per node; F=256 -> two float4 per lane. h row never hits DRAM:
// it is accumulated straight into the L2-resident pool buffer.
__global__ void gather2_pool_kernel(const float* __restrict__ b2,
                                    const int* __restrict__ batch) {
    int n = (blockIdx.x * blockDim.x + threadIdx.x) >> 5;
    if (n >= NN) return;
    int lane = threadIdx.x & 31;
    int e = g_rowptr[n];
    int end = g_rowptr[n + 1];
    float4 a0 = make_float4(0.f, 0.f, 0.f, 0.f);
    float4 a1 = make_float4(0.f, 0.f, 0.f, 0.f);
    for (; e < end; e++) {
        int s = g_csr_src[e]; float c = g_csr_coef[e];
        const float4* row = (const float4*)(g_xw2 + (size_t)s * F_H2);
        float4 v0 = row[lane];
        float4 v1 = row[lane + 32];
        a0.x += v0.x * c; a0.y += v0.y * c; a0.z += v0.z * c; a0.w += v0.w * c;
        a1.x += v1.x * c; a1.y += v1.y * c; a1.z += v1.z * c; a1.w += v1.w * c;
    }
    float d = g_dinv[n];
    float dd = d * d;
    const float4* srow = (const float4*)(g_xw2 + (size_t)n * F_H2);
    float4 s0 = srow[lane], s1 = srow[lane + 32];
    float4 b0 = ((const float4*)b2)[lane];
    float4 b1v = ((const float4*)b2)[lane + 32];
    a0.x += fmaf(s0.x, dd, b0.x);  a0.y += fmaf(s0.y, dd, b0.y);
    a0.z += fmaf(s0.z, dd, b0.z);  a0.w += fmaf(s0.w, dd, b0.w);
    a1.x += fmaf(s1.x, dd, b1v.x); a1.y += fmaf(s1.y, dd, b1v.y);
    a1.z += fmaf(s1.z, dd, b1v.z); a1.w += fmaf(s1.w, dd, b1v.w);

    int g = batch[n];
    float* pr = g_pool + (size_t)g * F_H2;
    float* p0 = pr + lane * 4;
    float* p1 = pr + (lane + 32) * 4;
    atomicAdd(p0 + 0, a0.x); atomicAdd(p0 + 1, a0.y);
    atomicAdd(p0 + 2, a0.z); atomicAdd(p0 + 3, a0.w);
    atomicAdd(p1 + 0, a1.x); atomicAdd(p1 + 1, a1.y);
    atomicAdd(p1 + 2, a1.z); atomicAdd(p1 + 3, a1.w);
    if (lane == 0) atomicAdd(&g_cnt[g], 1.0f);
}

// ---------------- heads: group + family logits ----------------
__global__ void logits_kernel(const float* __restrict__ Wg, const float* __restrict__ bg,
                              const float* __restrict__ Wf, const float* __restrict__ bf,
                              float* __restrict__ out) {
    __shared__ float p[F_H2];
    int b = blockIdx.x;       // graph
    int t = threadIdx.x;      // 256
    float cnt = fmaxf(g_cnt[b], 1.0f);
    p[t] = g_pool[b * F_H2 + t] / cnt;
    __syncthreads();

    if (t < N_GROUPS) {
        float s = bg[t];
#pragma unroll 8
        for (int k = 0; k < F_H2; k++) s = fmaf(p[k], Wg[k * N_GROUPS + t], s);
        out[b * N_GROUPS + t] = s;
    }
    if (t < N_GROUPS * N_FAM) {
        int g = t / N_FAM, f = t - g * N_FAM;
        float s = bf[g * N_FAM + f];
        const float* w = Wf + (size_t)g * F_H2 * N_FAM + f;
#pragma unroll 8
        for (int k = 0; k < F_H2; k++) s = fmaf(p[k], w[k * N_FAM], s);
        out[NG * N_GROUPS + (size_t)g * NG * N_FAM + b * N_FAM + f] = s;
    }
}

// ---------------- launcher ----------------
extern "C" void kernel_launch(void* const* d_in, const int* in_sizes, int n_in,
                              void* d_out, int out_size) {
    const float* x     = (const float*)d_in[0];
    const int*   ei    = (const int*)d_in[1];     // [2, NE] int32
    const int*   batch = (const int*)d_in[2];
    const float* W1    = (const float*)d_in[3];
    const float* b1    = (const float*)d_in[4];
    const float* W2    = (const float*)d_in[5];
    const float* b2    = (const float*)d_in[6];
    const float* Wg    = (const float*)d_in[7];
    const float* bg    = (const float*)d_in[8];
    const float* Wf    = (const float*)d_in[9];
    const float* bf    = (const float*)d_in[10];
    float* out = (float*)d_out;

    const int* src = ei;
    const int* dst = ei + NE;

    float *xw1, *agg1, *xw2;
    cudaGetSymbolAddress((void**)&xw1,  g_xw1);
    cudaGetSymbolAddress((void**)&agg1, g_agg1);
    cudaGetSymbolAddress((void**)&xw2,  g_xw2);

    // degree histogram + dinv + CSR build (scatter -> gather transform)
    zero_kernel<<<(NG * F_H2 + 255) / 256, 256>>>();
    hist_kernel<<<(NE + 255) / 256, 256>>>(dst);
    dinv_kernel<<<(NN + 255) / 256, 256>>>();
    scan_block_kernel<<<NBLK_SCAN, SCAN_BLK>>>();
    scan_sums_kernel<<<1, 512>>>();
    scan_add_kernel<<<(NN + 255) / 256, 256>>>();
    csr_fill_kernel<<<(NE + 255) / 256, 256>>>(src, dst);

    // layer 1: xw1 = x @ W1 ; gather (fused self-loop + bias)
    gemm_kernel<<<dim3((NN + GBM - 1) / GBM, F_H1 / GBN), 256>>>(x, W1, xw1, NN, F_H1, F_IN, 0);
    gather1_kernel<<<(NN * 32 + 255) / 256, 256>>>(b1);

    // layer 2: xw2 = relu(agg1) @ W2 ; gather fused with mean-pool accumulation
    gemm_kernel<<<dim3((NN + GBM - 1) / GBM, F_H2 / GBN), 256>>>(agg1, W2, xw2, NN, F_H2, F_H1, 1);
    gather2_pool_kernel<<<(NN * 32 + 255) / 256, 256>>>(b2, batch);

    // heads
    logits_kernel<<<NG, F_H2>>>(Wg, bg, Wf, bf, out);
}

// round 8
// speedup vs baseline: 5.1753x; 1.7610x over previous
#include <cuda_runtime.h>

#define NN 100000
#define NE 1600000
#define NG 512
#define F_IN 128
#define F_H1 128
#define F_H2 256
#define N_GROUPS 16
#define N_FAM 10

#define SCAN_BLK 256
#define NBLK_SCAN ((NN + SCAN_BLK - 1) / SCAN_BLK)   // 391

// ---------------- scratch (device globals: allocation-guard-safe) ----------------
__device__ float g_xw1[(size_t)NN * F_H1];   // x @ W1
__device__ float g_agg1[(size_t)NN * F_H1];  // layer-1 aggregation (pre-relu)
__device__ float g_dinv[NN];                 // rsqrt(deg+1)
__device__ int   g_deg[NN];                  // in-degree histogram
__device__ int   g_rowptr[NN + 1];           // CSR row pointers (by dst)
__device__ int   g_fill[NN];                 // running fill cursors
__device__ int   g_blocksum[NBLK_SCAN + 1];  // scan partials
__device__ int   g_csr_src[NE];              // src ids, dst-ordered
__device__ float g_csr_coef[NE];             // edge coefficients, dst-ordered
__device__ float g_pool[NG * F_H1];          // pooled (P*A*relu(agg1)) sums [512,128]
__device__ float g_cnt[NG];                  // segment counts

// ---------------- zero + degree histogram + normalization ----------------
// NOTE: must be launched with >= NN threads (covers g_deg fully!) — replay
// correctness depends on the histogram being re-zeroed every call.
__global__ void zero_kernel() {
    int i = blockIdx.x * blockDim.x + threadIdx.x;
    if (i < NN) g_deg[i] = 0;
    if (i < NG * F_H1) g_pool[i] = 0.f;
    if (i < NG) g_cnt[i] = 0.f;
}

__global__ void hist_kernel(const int* __restrict__ dst) {
    int e = blockIdx.x * blockDim.x + threadIdx.x;
    if (e < NE) atomicAdd(&g_deg[dst[e]], 1);
}

__global__ void dinv_kernel() {
    int i = blockIdx.x * blockDim.x + threadIdx.x;
    if (i < NN) g_dinv[i] = rsqrtf((float)g_deg[i] + 1.0f);
}

// ---------------- exclusive scan of g_deg -> g_rowptr ----------------
__global__ void scan_block_kernel() {
    __shared__ int s[SCAN_BLK];
    int tid = threadIdx.x;
    int i = blockIdx.x * SCAN_BLK + tid;
    int v = (i < NN) ? g_deg[i] : 0;
    s[tid] = v;
    __syncthreads();
#pragma unroll
    for (int off = 1; off < SCAN_BLK; off <<= 1) {
        int t = (tid >= off) ? s[tid - off] : 0;
        __syncthreads();
        s[tid] += t;
        __syncthreads();
    }
    if (i < NN) g_rowptr[i] = s[tid] - v;      // exclusive within block
    if (tid == SCAN_BLK - 1) g_blocksum[blockIdx.x] = s[tid];
}

__global__ void scan_sums_kernel() {
    __shared__ int s[512];
    int tid = threadIdx.x;                      // 512 threads
    int v = (tid < NBLK_SCAN) ? g_blocksum[tid] : 0;
    s[tid] = v;
    __syncthreads();
#pragma unroll
    for (int off = 1; off < 512; off <<= 1) {
        int t = (tid >= off) ? s[tid - off] : 0;
        __syncthreads();
        s[tid] += t;
        __syncthreads();
    }
    if (tid < NBLK_SCAN) g_blocksum[tid] = s[tid] - v;   // exclusive
}

__global__ void scan_add_kernel() {
    int i = blockIdx.x * blockDim.x + threadIdx.x;
    if (i < NN) {
        int r = g_rowptr[i] + g_blocksum[i / SCAN_BLK];
        g_rowptr[i] = r;
        g_fill[i] = r;
    }
    if (i == 0) g_rowptr[NN] = NE;
}

// ---------------- CSR fill (dst-ordered src + coef) ----------------
__global__ void csr_fill_kernel(const int* __restrict__ src, const int* __restrict__ dst) {
    int e = blockIdx.x * blockDim.x + threadIdx.x;
    if (e >= NE) return;
    int s = src[e], d = dst[e];
    int pos = atomicAdd(&g_fill[d], 1);
    g_csr_src[pos] = s;
    g_csr_coef[pos] = g_dinv[s] * g_dinv[d];
}

// ---------------- GEMM: C[M,N] = A[M,K] @ B[K,N] ----------------
#define GBM 64
#define GBN 64
#define GBK 32
__global__ void gemm_kernel(const float* __restrict__ A, const float* __restrict__ B,
                            float* __restrict__ C, int M, int N, int K) {
    __shared__ float As[GBK][GBM + 4];
    __shared__ float Bs[GBK][GBN + 4];
    int tid = threadIdx.x;            // 256 threads
    int bm = blockIdx.x * GBM;
    int bn = blockIdx.y * GBN;
    int trow = (tid >> 4) * 4;        // 16x16 thread grid, 4x4 micro-tile
    int tcol = (tid & 15) * 4;
    float acc[4][4];
#pragma unroll
    for (int i = 0; i < 4; i++)
#pragma unroll
        for (int j = 0; j < 4; j++) acc[i][j] = 0.f;

    for (int k0 = 0; k0 < K; k0 += GBK) {
        for (int i = tid; i < GBM * GBK; i += 256) {
            int m = i >> 5, k = i & 31;
            int gm = bm + m;
            As[k][m] = (gm < M) ? A[(size_t)gm * K + k0 + k] : 0.f;
        }
        for (int i = tid; i < GBK * GBN; i += 256) {
            int k = i >> 6, n = i & 63;
            Bs[k][n] = B[(size_t)(k0 + k) * N + bn + n];
        }
        __syncthreads();
#pragma unroll
        for (int k = 0; k < GBK; k++) {
            float a[4], b[4];
#pragma unroll
            for (int i = 0; i < 4; i++) a[i] = As[k][trow + i];
#pragma unroll
            for (int j = 0; j < 4; j++) b[j] = Bs[k][tcol + j];
#pragma unroll
            for (int i = 0; i < 4; i++)
#pragma unroll
                for (int j = 0; j < 4; j++) acc[i][j] += a[i] * b[j];
        }
        __syncthreads();
    }
#pragma unroll
    for (int i = 0; i < 4; i++) {
        int gm = bm + trow + i;
        if (gm < M) {
#pragma unroll
            for (int j = 0; j < 4; j++)
                C[(size_t)gm * N + bn + tcol + j] = acc[i][j];
        }
    }
}

// ---------------- layer-1 gather: agg1[n] = sum_in xw1[src]*coef + xw1[n]*dinv^2 + b1 ----------------
__global__ void gather1_kernel(const float* __restrict__ b1) {
    int n = (blockIdx.x * blockDim.x + threadIdx.x) >> 5;
    if (n >= NN) return;
    int lane = threadIdx.x & 31;
    int e = g_rowptr[n];
    int end = g_rowptr[n + 1];
    float4 acc = make_float4(0.f, 0.f, 0.f, 0.f);
    for (; e + 1 < end; e += 2) {
        int s0 = g_csr_src[e];     float c0 = g_csr_coef[e];
        int s1 = g_csr_src[e + 1]; float c1 = g_csr_coef[e + 1];
        float4 v0 = ((const float4*)(g_xw1 + (size_t)s0 * F_H1))[lane];
        float4 v1 = ((const float4*)(g_xw1 + (size_t)s1 * F_H1))[lane];
        acc.x += v0.x * c0 + v1.x * c1;
        acc.y += v0.y * c0 + v1.y * c1;
        acc.z += v0.z * c0 + v1.z * c1;
        acc.w += v0.w * c0 + v1.w * c1;
    }
    if (e < end) {
        int s0 = g_csr_src[e]; float c0 = g_csr_coef[e];
        float4 v0 = ((const float4*)(g_xw1 + (size_t)s0 * F_H1))[lane];
        acc.x += v0.x * c0; acc.y += v0.y * c0; acc.z += v0.z * c0; acc.w += v0.w * c0;
    }
    float d = g_dinv[n];
    float dd = d * d;
    float4 self = ((const float4*)(g_xw1 + (size_t)n * F_H1))[lane];
    float4 bb = ((const float4*)b1)[lane];
    float4 o;
    o.x = acc.x + fmaf(self.x, dd, bb.x);
    o.y = acc.y + fmaf(self.y, dd, bb.y);
    o.z = acc.z + fmaf(self.z, dd, bb.z);
    o.w = acc.w + fmaf(self.w, dd, bb.w);
    ((float4*)(g_agg1 + (size_t)n * F_H1))[lane] = o;
}

// ---------------- layer-2 gather (pre-projection!) + fused pooling ----------------
// Aggregation commutes with @W2: pooled = (P * A_hat * relu(agg1)) @ W2 + ...
// So gather over F=128 relu(agg1) rows and accumulate straight into the
// [512,128] pool buffer. Layer-2 node rows never touch DRAM; @W2 is per-graph later.
__global__ void gather2_pool_kernel(const int* __restrict__ batch) {
    int n = (blockIdx.x * blockDim.x + threadIdx.x) >> 5;
    if (n >= NN) return;
    int lane = threadIdx.x & 31;
    int e = g_rowptr[n];
    int end = g_rowptr[n + 1];
    float4 acc = make_float4(0.f, 0.f, 0.f, 0.f);
    for (; e + 1 < end; e += 2) {
        int s0 = g_csr_src[e];     float c0 = g_csr_coef[e];
        int s1 = g_csr_src[e + 1]; float c1 = g_csr_coef[e + 1];
        float4 v0 = ((const float4*)(g_agg1 + (size_t)s0 * F_H1))[lane];
        float4 v1 = ((const float4*)(g_agg1 + (size_t)s1 * F_H1))[lane];
        acc.x += fmaxf(v0.x, 0.f) * c0 + fmaxf(v1.x, 0.f) * c1;
        acc.y += fmaxf(v0.y, 0.f) * c0 + fmaxf(v1.y, 0.f) * c1;
        acc.z += fmaxf(v0.z, 0.f) * c0 + fmaxf(v1.z, 0.f) * c1;
        acc.w += fmaxf(v0.w, 0.f) * c0 + fmaxf(v1.w, 0.f) * c1;
    }
    if (e < end) {
        int s0 = g_csr_src[e]; float c0 = g_csr_coef[e];
        float4 v0 = ((const float4*)(g_agg1 + (size_t)s0 * F_H1))[lane];
        acc.x += fmaxf(v0.x, 0.f) * c0;
        acc.y += fmaxf(v0.y, 0.f) * c0;
        acc.z += fmaxf(v0.z, 0.f) * c0;
        acc.w += fmaxf(v0.w, 0.f) * c0;
    }
    float d = g_dinv[n];
    float dd = d * d;
    float4 self = ((const float4*)(g_agg1 + (size_t)n * F_H1))[lane];
    acc.x += fmaxf(self.x, 0.f) * dd;
    acc.y += fmaxf(self.y, 0.f) * dd;
    acc.z += fmaxf(self.z, 0.f) * dd;
    acc.w += fmaxf(self.w, 0.f) * dd;

    int g = batch[n];
    float* p = g_pool + (size_t)g * F_H1 + lane * 4;
    atomicAdd(p + 0, acc.x);
    atomicAdd(p + 1, acc.y);
    atomicAdd(p + 2, acc.z);
    atomicAdd(p + 3, acc.w);
    if (lane == 0) atomicAdd(&g_cnt[g], 1.0f);
}

// ---------------- heads: tiny @W2+b2 per graph, then group + family logits ----------------
__global__ void logits_kernel(const float* __restrict__ W2, const float* __restrict__ b2,
                              const float* __restrict__ Wg, const float* __restrict__ bg,
                              const float* __restrict__ Wf, const float* __restrict__ bf,
                              float* __restrict__ out) {
    __shared__ float p[F_H1];    // pooled mean of A_hat*relu(agg1), [128]
    __shared__ float h2[F_H2];   // pooled @ W2 + b2, [256]
    int b = blockIdx.x;          // graph
    int t = threadIdx.x;         // 256 threads
    float cnt = fmaxf(g_cnt[b], 1.0f);
    if (t < F_H1) p[t] = g_pool[b * F_H1 + t] / cnt;
    __syncthreads();

    // h2[t] = b2[t] + sum_k p[k] * W2[k][t]   (W2 row-major [128,256], coalesced over t)
    {
        float s = b2[t];
#pragma unroll 8
        for (int k = 0; k < F_H1; k++) s = fmaf(p[k], W2[k * F_H2 + t], s);
        h2[t] = s;
    }
    __syncthreads();

    if (t < N_GROUPS) {
        float s = bg[t];
#pragma unroll 8
        for (int k = 0; k < F_H2; k++) s = fmaf(h2[k], Wg[k * N_GROUPS + t], s);
        out[b * N_GROUPS + t] = s;
    }
    if (t < N_GROUPS * N_FAM) {
        int g = t / N_FAM, f = t - g * N_FAM;
        float s = bf[g * N_FAM + f];
        const float* w = Wf + (size_t)g * F_H2 * N_FAM + f;
#pragma unroll 8
        for (int k = 0; k < F_H2; k++) s = fmaf(h2[k], w[k * N_FAM], s);
        out[NG * N_GROUPS + (size_t)g * NG * N_FAM + b * N_FAM + f] = s;
    }
}

// ---------------- launcher ----------------
extern "C" void kernel_launch(void* const* d_in, const int* in_sizes, int n_in,
                              void* d_out, int out_size) {
    const float* x     = (const float*)d_in[0];
    const int*   ei    = (const int*)d_in[1];     // [2, NE] int32
    const int*   batch = (const int*)d_in[2];
    const float* W1    = (const float*)d_in[3];
    const float* b1    = (const float*)d_in[4];
    const float* W2    = (const float*)d_in[5];
    const float* b2    = (const float*)d_in[6];
    const float* Wg    = (const float*)d_in[7];
    const float* bg    = (const float*)d_in[8];
    const float* Wf    = (const float*)d_in[9];
    const float* bf    = (const float*)d_in[10];
    float* out = (float*)d_out;

    const int* src = ei;
    const int* dst = ei + NE;

    float* xw1;
    cudaGetSymbolAddress((void**)&xw1, g_xw1);

    // degree histogram + dinv + CSR build
    // zero_kernel MUST cover NN elements (g_deg) — replay-idempotence bug fix.
    zero_kernel<<<(NN + 255) / 256, 256>>>();
    hist_kernel<<<(NE + 255) / 256, 256>>>(dst);
    dinv_kernel<<<(NN + 255) / 256, 256>>>();
    scan_block_kernel<<<NBLK_SCAN, SCAN_BLK>>>();
    scan_sums_kernel<<<1, 512>>>();
    scan_add_kernel<<<(NN + 255) / 256, 256>>>();
    csr_fill_kernel<<<(NE + 255) / 256, 256>>>(src, dst);

    // layer 1: xw1 = x @ W1 ; gather (fused self-loop + bias)
    gemm_kernel<<<dim3((NN + GBM - 1) / GBM, F_H1 / GBN), 256>>>(x, W1, xw1, NN, F_H1, F_IN);
    gather1_kernel<<<(NN * 32 + 255) / 256, 256>>>(b1);

    // layer 2 (reassociated): pool(A_hat * relu(agg1)) with relu fused; @W2 deferred to heads
    gather2_pool_kernel<<<(NN * 32 + 255) / 256, 256>>>(batch);

    // heads: per-graph @W2+b2 then logits
    logits_kernel<<<NG, F_H2>>>(W2, b2, Wg, bg, Wf, bf, out);
}

// round 10
// speedup vs baseline: 5.8000x; 1.1207x over previous
#include <cuda_runtime.h>

#define NN 100000
#define NE 1600000
#define NG 512
#define F_IN 128
#define F_H1 128
#define F_H2 256
#define N_GROUPS 16
#define N_FAM 10

#define SCAN_BLK 256
#define NBLK_SCAN ((NN + SCAN_BLK - 1) / SCAN_BLK)   // 391

// ---------------- scratch (device globals: allocation-guard-safe) ----------------
__device__ float g_xw1s[(size_t)NN * F_H1];  // dinv * (x @ W1)   (prescaled)
__device__ float g_h1s[(size_t)NN * F_H1];   // dinv * relu(agg1) (prescaled layer-1 output)
__device__ float g_dinv[NN];                 // rsqrt(deg+1)
__device__ int   g_deg[NN];                  // in-degree histogram
__device__ int   g_rowptr[NN + 1];           // CSR row pointers (by dst)
__device__ int   g_fill[NN];                 // running fill cursors
__device__ int   g_blocksum[NBLK_SCAN + 1];  // scan partials
__device__ int   g_csr_src[NE];              // src ids, dst-ordered (no coef array needed)
__device__ float g_pool[NG * F_H1];          // pooled (P*A*relu(agg1)) sums [512,128]
__device__ float g_cnt[NG];                  // segment counts

// ---------------- zero + degree histogram ----------------
// NOTE: must cover NN threads (g_deg) — replay idempotence.
__global__ void zero_kernel() {
    int i = blockIdx.x * blockDim.x + threadIdx.x;
    if (i < NN) g_deg[i] = 0;
    if (i < NG * F_H1) g_pool[i] = 0.f;
    if (i < NG) g_cnt[i] = 0.f;
}

__global__ void hist_kernel(const int* __restrict__ dst) {
    int e = blockIdx.x * blockDim.x + threadIdx.x;
    if (e < NE) atomicAdd(&g_deg[dst[e]], 1);
}

// ---------------- exclusive scan of g_deg -> g_rowptr (dinv fused in) ----------------
__global__ void scan_block_kernel() {
    __shared__ int s[SCAN_BLK];
    int tid = threadIdx.x;
    int i = blockIdx.x * SCAN_BLK + tid;
    int v = (i < NN) ? g_deg[i] : 0;
    if (i < NN) g_dinv[i] = rsqrtf((float)v + 1.0f);   // fused dinv
    s[tid] = v;
    __syncthreads();
#pragma unroll
    for (int off = 1; off < SCAN_BLK; off <<= 1) {
        int t = (tid >= off) ? s[tid - off] : 0;
        __syncthreads();
        s[tid] += t;
        __syncthreads();
    }
    if (i < NN) g_rowptr[i] = s[tid] - v;      // exclusive within block
    if (tid == SCAN_BLK - 1) g_blocksum[blockIdx.x] = s[tid];
}

__global__ void scan_sums_kernel() {
    __shared__ int s[512];
    int tid = threadIdx.x;                      // 512 threads
    int v = (tid < NBLK_SCAN) ? g_blocksum[tid] : 0;
    s[tid] = v;
    __syncthreads();
#pragma unroll
    for (int off = 1; off < 512; off <<= 1) {
        int t = (tid >= off) ? s[tid - off] : 0;
        __syncthreads();
        s[tid] += t;
        __syncthreads();
    }
    if (tid < NBLK_SCAN) g_blocksum[tid] = s[tid] - v;   // exclusive
}

__global__ void scan_add_kernel() {
    int i = blockIdx.x * blockDim.x + threadIdx.x;
    if (i < NN) {
        int r = g_rowptr[i] + g_blocksum[i / SCAN_BLK];
        g_rowptr[i] = r;
        g_fill[i] = r;
    }
    if (i == 0) g_rowptr[NN] = NE;
}

// ---------------- CSR fill (src ids only — coef factored out algebraically) ----------------
__global__ void csr_fill_kernel(const int* __restrict__ src, const int* __restrict__ dst) {
    int e = blockIdx.x * blockDim.x + threadIdx.x;
    if (e >= NE) return;
    int pos = atomicAdd(&g_fill[dst[e]], 1);
    g_csr_src[pos] = src[e];
}

// ---------------- GEMM1: xw1s = dinv * (x @ W1); N=K=128 fixed ----------------
// 128x128x16 tiles, 256 threads, 8x8 micro-tile: 4 FMA per LDS float (FMA-balanced).
#define TBM 128
#define TBK 16
__global__ __launch_bounds__(256) void gemm1_kernel(const float* __restrict__ A,
                                                    const float* __restrict__ B,
                                                    float* __restrict__ C, int M) {
    __shared__ float As[TBK][TBM + 4];
    __shared__ float Bs[TBK][TBM + 4];
    int tid = threadIdx.x;
    int bm = blockIdx.x * TBM;
    int trow = (tid >> 4) * 8;
    int tcol = (tid & 15) * 8;
    float acc[8][8];
#pragma unroll
    for (int i = 0; i < 8; i++)
#pragma unroll
        for (int j = 0; j < 8; j++) acc[i][j] = 0.f;

    for (int k0 = 0; k0 < 128; k0 += TBK) {
        // A tile: 128 rows x 16 k = 512 float4 (each float4 = 4 consecutive k)
#pragma unroll
        for (int i = tid; i < TBM * 4; i += 256) {
            int m = i >> 2, kq = i & 3;
            int gm = bm + m;
            float4 v = (gm < M) ? ((const float4*)(A + (size_t)gm * 128 + k0))[kq]
                                : make_float4(0.f, 0.f, 0.f, 0.f);
            As[kq * 4 + 0][m] = v.x;
            As[kq * 4 + 1][m] = v.y;
            As[kq * 4 + 2][m] = v.z;
            As[kq * 4 + 3][m] = v.w;
        }
        // B tile: 16 k-rows x 128 = 512 float4, fully coalesced
#pragma unroll
        for (int i = tid; i < TBK * 32; i += 256) {
            int k = i >> 5, nq = i & 31;
            float4 v = ((const float4*)(B + (size_t)(k0 + k) * 128))[nq];
            *(float4*)&Bs[k][nq * 4] = v;
        }
        __syncthreads();
#pragma unroll
        for (int k = 0; k < TBK; k++) {
            float a[8], b[8];
            *(float4*)&a[0] = *(const float4*)&As[k][trow];
            *(float4*)&a[4] = *(const float4*)&As[k][trow + 4];
            *(float4*)&b[0] = *(const float4*)&Bs[k][tcol];
            *(float4*)&b[4] = *(const float4*)&Bs[k][tcol + 4];
#pragma unroll
            for (int i = 0; i < 8; i++)
#pragma unroll
                for (int j = 0; j < 8; j++) acc[i][j] = fmaf(a[i], b[j], acc[i][j]);
        }
        __syncthreads();
    }
#pragma unroll
    for (int i = 0; i < 8; i++) {
        int gm = bm + trow + i;
        if (gm < M) {
            float d = g_dinv[gm];                 // prescale epilogue (free)
            float4 o0, o1;
            o0.x = acc[i][0] * d; o0.y = acc[i][1] * d;
            o0.z = acc[i][2] * d; o0.w = acc[i][3] * d;
            o1.x = acc[i][4] * d; o1.y = acc[i][5] * d;
            o1.z = acc[i][6] * d; o1.w = acc[i][7] * d;
            float* cr = C + (size_t)gm * 128 + tcol;
            *(float4*)cr = o0;
            *(float4*)(cr + 4) = o1;
        }
    }
}

// ---------------- layer-1 gather: h1s[n] = dinv[n]*relu(dinv[n]*(sum xw1s[s] + xw1s[n]) + b1) ----------------
__global__ void gather1_kernel(const float* __restrict__ b1) {
    int n = (blockIdx.x * blockDim.x + threadIdx.x) >> 5;
    if (n >= NN) return;
    int lane = threadIdx.x & 31;
    int e = g_rowptr[n];
    int end = g_rowptr[n + 1];
    float4 acc = make_float4(0.f, 0.f, 0.f, 0.f);
    for (; e + 1 < end; e += 2) {
        int s0 = g_csr_src[e];
        int s1 = g_csr_src[e + 1];
        float4 v0 = ((const float4*)(g_xw1s + (size_t)s0 * F_H1))[lane];
        float4 v1 = ((const float4*)(g_xw1s + (size_t)s1 * F_H1))[lane];
        acc.x += v0.x + v1.x;
        acc.y += v0.y + v1.y;
        acc.z += v0.z + v1.z;
        acc.w += v0.w + v1.w;
    }
    if (e < end) {
        int s0 = g_csr_src[e];
        float4 v0 = ((const float4*)(g_xw1s + (size_t)s0 * F_H1))[lane];
        acc.x += v0.x; acc.y += v0.y; acc.z += v0.z; acc.w += v0.w;
    }
    float d = g_dinv[n];
    float4 self = ((const float4*)(g_xw1s + (size_t)n * F_H1))[lane];
    float4 bb = ((const float4*)b1)[lane];
    float4 o;
    o.x = d * fmaxf(fmaf(acc.x + self.x, d, bb.x), 0.f);
    o.y = d * fmaxf(fmaf(acc.y + self.y, d, bb.y), 0.f);
    o.z = d * fmaxf(fmaf(acc.z + self.z, d, bb.z), 0.f);
    o.w = d * fmaxf(fmaf(acc.w + self.w, d, bb.w), 0.f);
    ((float4*)(g_h1s + (size_t)n * F_H1))[lane] = o;
}

// ---------------- layer-2 gather + fused pooling: pool[g] += dinv[n]*(sum h1s[s] + h1s[n]) ----------------
__global__ void gather2_pool_kernel(const int* __restrict__ batch) {
    int n = (blockIdx.x * blockDim.x + threadIdx.x) >> 5;
    if (n >= NN) return;
    int lane = threadIdx.x & 31;
    int e = g_rowptr[n];
    int end = g_rowptr[n + 1];
    float4 acc = make_float4(0.f, 0.f, 0.f, 0.f);
    for (; e + 1 < end; e += 2) {
        int s0 = g_csr_src[e];
        int s1 = g_csr_src[e + 1];
        float4 v0 = ((const float4*)(g_h1s + (size_t)s0 * F_H1))[lane];
        float4 v1 = ((const float4*)(g_h1s + (size_t)s1 * F_H1))[lane];
        acc.x += v0.x + v1.x;
        acc.y += v0.y + v1.y;
        acc.z += v0.z + v1.z;
        acc.w += v0.w + v1.w;
    }
    if (e < end) {
        int s0 = g_csr_src[e];
        float4 v0 = ((const float4*)(g_h1s + (size_t)s0 * F_H1))[lane];
        acc.x += v0.x; acc.y += v0.y; acc.z += v0.z; acc.w += v0.w;
    }
    float d = g_dinv[n];
    float4 self = ((const float4*)(g_h1s + (size_t)n * F_H1))[lane];
    acc.x = (acc.x + self.x) * d;
    acc.y = (acc.y + self.y) * d;
    acc.z = (acc.z + self.z) * d;
    acc.w = (acc.w + self.w) * d;

    int g = batch[n];
    float* p = g_pool + (size_t)g * F_H1 + lane * 4;
    atomicAdd(p + 0, acc.x);
    atomicAdd(p + 1, acc.y);
    atomicAdd(p + 2, acc.z);
    atomicAdd(p + 3, acc.w);
    if (lane == 0) atomicAdd(&g_cnt[g], 1.0f);
}

// ---------------- heads: tiny @W2+b2 per graph, then group + family logits ----------------
__global__ void logits_kernel(const float* __restrict__ W2, const float* __restrict__ b2,
                              const float* __restrict__ Wg, const float* __restrict__ bg,
                              const float* __restrict__ Wf, const float* __restrict__ bf,
                              float* __restrict__ out) {
    __shared__ float p[F_H1];    // pooled mean, [128]
    __shared__ float h2[F_H2];   // pooled @ W2 + b2, [256]
    int b = blockIdx.x;          // graph
    int t = threadIdx.x;         // 256 threads
    float cnt = fmaxf(g_cnt[b], 1.0f);
    if (t < F_H1) p[t] = g_pool[b * F_H1 + t] / cnt;
    __syncthreads();

    {
        float s = b2[t];
#pragma unroll 8
        for (int k = 0; k < F_H1; k++) s = fmaf(p[k], W2[k * F_H2 + t], s);
        h2[t] = s;
    }
    __syncthreads();

    if (t < N_GROUPS) {
        float s = bg[t];
#pragma unroll 8
        for (int k = 0; k < F_H2; k++) s = fmaf(h2[k], Wg[k * N_GROUPS + t], s);
        out[b * N_GROUPS + t] = s;
    }
    if (t < N_GROUPS * N_FAM) {
        int g = t / N_FAM, f = t - g * N_FAM;
        float s = bf[g * N_FAM + f];
        const float* w = Wf + (size_t)g * F_H2 * N_FAM + f;
#pragma unroll 8
        for (int k = 0; k < F_H2; k++) s = fmaf(h2[k], w[k * N_FAM], s);
        out[NG * N_GROUPS + (size_t)g * NG * N_FAM + b * N_FAM + f] = s;
    }
}

// ---------------- launcher ----------------
extern "C" void kernel_launch(void* const* d_in, const int* in_sizes, int n_in,
                              void* d_out, int out_size) {
    const float* x     = (const float*)d_in[0];
    const int*   ei    = (const int*)d_in[1];     // [2, NE] int32
    const int*   batch = (const int*)d_in[2];
    const float* W1    = (const float*)d_in[3];
    const float* b1    = (const float*)d_in[4];
    const float* W2    = (const float*)d_in[5];
    const float* b2    = (const float*)d_in[6];
    const float* Wg    = (const float*)d_in[7];
    const float* bg    = (const float*)d_in[8];
    const float* Wf    = (const float*)d_in[9];
    const float* bf    = (const float*)d_in[10];
    float* out = (float*)d_out;

    const int* src = ei;
    const int* dst = ei + NE;

    float* xw1s;
    cudaGetSymbolAddress((void**)&xw1s, g_xw1s);

    // degree histogram + scan(+dinv) + CSR fill
    zero_kernel<<<(NN + 255) / 256, 256>>>();
    hist_kernel<<<(NE + 255) / 256, 256>>>(dst);
    scan_block_kernel<<<NBLK_SCAN, SCAN_BLK>>>();
    scan_sums_kernel<<<1, 512>>>();
    scan_add_kernel<<<(NN + 255) / 256, 256>>>();
    csr_fill_kernel<<<(NE + 255) / 256, 256>>>(src, dst);

    // layer 1: xw1s = dinv * (x @ W1); gather -> h1s = dinv*relu(agg1)
    gemm1_kernel<<<(NN + TBM - 1) / TBM, 256>>>(x, W1, xw1s, NN);
    gather1_kernel<<<(NN * 32 + 255) / 256, 256>>>(b1);

    // layer 2 (reassociated): pool(A_hat * relu(agg1)); @W2 deferred to heads
    gather2_pool_kernel<<<(NN * 32 + 255) / 256, 256>>>(batch);

    // heads: per-graph @W2+b2 then logits
    logits_kernel<<<NG, F_H2>>>(W2, b2, Wg, bg, Wf, bf, out);
}

// round 11
// speedup vs baseline: 6.5433x; 1.1282x over previous
#include <cuda_runtime.h>
#include <cuda_fp16.h>

#define NN 100000
#define NE 1600000
#define NG 512
#define F_IN 128
#define F_H1 128
#define F_H2 256
#define N_GROUPS 16
#define N_FAM 10

#define SCAN_BLK 256
#define NBLK_SCAN ((NN + SCAN_BLK - 1) / SCAN_BLK)   // 391

// ---------------- scratch (device globals: allocation-guard-safe) ----------------
__device__ __half g_xw1s[(size_t)NN * F_H1]; // dinv * (x @ W1), fp16 (25.6 MB, L2-resident)
__device__ __half g_h1s[(size_t)NN * F_H1];  // dinv * relu(agg1), fp16 (25.6 MB, L2-resident)
__device__ float g_dinv[NN];                 // rsqrt(deg+1)
__device__ int   g_deg[NN];                  // in-degree histogram
__device__ int   g_rowptr[NN + 1];           // CSR row pointers (by dst)
__device__ int   g_fill[NN];                 // running fill cursors
__device__ int   g_blocksum[NBLK_SCAN + 1];  // scan partials
__device__ int   g_csr_src[NE];              // src ids, dst-ordered
__device__ float g_pool[NG * F_H1];          // pooled sums [512,128] (fp32)
__device__ float g_cnt[NG];                  // segment counts

// ---------------- zero + degree histogram ----------------
// NOTE: must cover NN threads (g_deg) — replay idempotence.
__global__ void zero_kernel() {
    int i = blockIdx.x * blockDim.x + threadIdx.x;
    if (i < NN) g_deg[i] = 0;
    if (i < NG * F_H1) g_pool[i] = 0.f;
    if (i < NG) g_cnt[i] = 0.f;
}

__global__ void hist_kernel(const int* __restrict__ dst) {
    int e = blockIdx.x * blockDim.x + threadIdx.x;
    if (e < NE) atomicAdd(&g_deg[dst[e]], 1);
}

// ---------------- exclusive scan of g_deg -> g_rowptr (dinv fused in) ----------------
__global__ void scan_block_kernel() {
    __shared__ int s[SCAN_BLK];
    int tid = threadIdx.x;
    int i = blockIdx.x * SCAN_BLK + tid;
    int v = (i < NN) ? g_deg[i] : 0;
    if (i < NN) g_dinv[i] = rsqrtf((float)v + 1.0f);   // fused dinv
    s[tid] = v;
    __syncthreads();
#pragma unroll
    for (int off = 1; off < SCAN_BLK; off <<= 1) {
        int t = (tid >= off) ? s[tid - off] : 0;
        __syncthreads();
        s[tid] += t;
        __syncthreads();
    }
    if (i < NN) g_rowptr[i] = s[tid] - v;      // exclusive within block
    if (tid == SCAN_BLK - 1) g_blocksum[blockIdx.x] = s[tid];
}

__global__ void scan_sums_kernel() {
    __shared__ int s[512];
    int tid = threadIdx.x;                      // 512 threads
    int v = (tid < NBLK_SCAN) ? g_blocksum[tid] : 0;
    s[tid] = v;
    __syncthreads();
#pragma unroll
    for (int off = 1; off < 512; off <<= 1) {
        int t = (tid >= off) ? s[tid - off] : 0;
        __syncthreads();
        s[tid] += t;
        __syncthreads();
    }
    if (tid < NBLK_SCAN) g_blocksum[tid] = s[tid] - v;   // exclusive
}

__global__ void scan_add_kernel() {
    int i = blockIdx.x * blockDim.x + threadIdx.x;
    if (i < NN) {
        int r = g_rowptr[i] + g_blocksum[i / SCAN_BLK];
        g_rowptr[i] = r;
        g_fill[i] = r;
    }
    if (i == 0) g_rowptr[NN] = NE;
}

// ---------------- CSR fill (src ids only) ----------------
__global__ void csr_fill_kernel(const int* __restrict__ src, const int* __restrict__ dst) {
    int e = blockIdx.x * blockDim.x + threadIdx.x;
    if (e >= NE) return;
    int pos = atomicAdd(&g_fill[dst[e]], 1);
    g_csr_src[pos] = src[e];
}

// ---------------- GEMM1: xw1s = fp16(dinv * (x @ W1)); N=K=128 fixed ----------------
// 128x128x16 tiles, 256 threads, 8x8 micro-tile: 4 FMA per LDS float.
#define TBM 128
#define TBK 16
__global__ __launch_bounds__(256) void gemm1_kernel(const float* __restrict__ A,
                                                    const float* __restrict__ B,
                                                    __half* __restrict__ C, int M) {
    __shared__ float As[TBK][TBM + 4];
    __shared__ float Bs[TBK][TBM + 4];
    int tid = threadIdx.x;
    int bm = blockIdx.x * TBM;
    int trow = (tid >> 4) * 8;
    int tcol = (tid & 15) * 8;
    float acc[8][8];
#pragma unroll
    for (int i = 0; i < 8; i++)
#pragma unroll
        for (int j = 0; j < 8; j++) acc[i][j] = 0.f;

    for (int k0 = 0; k0 < 128; k0 += TBK) {
#pragma unroll
        for (int i = tid; i < TBM * 4; i += 256) {
            int m = i >> 2, kq = i & 3;
            int gm = bm + m;
            float4 v = (gm < M) ? ((const float4*)(A + (size_t)gm * 128 + k0))[kq]
                                : make_float4(0.f, 0.f, 0.f, 0.f);
            As[kq * 4 + 0][m] = v.x;
            As[kq * 4 + 1][m] = v.y;
            As[kq * 4 + 2][m] = v.z;
            As[kq * 4 + 3][m] = v.w;
        }
#pragma unroll
        for (int i = tid; i < TBK * 32; i += 256) {
            int k = i >> 5, nq = i & 31;
            float4 v = ((const float4*)(B + (size_t)(k0 + k) * 128))[nq];
            *(float4*)&Bs[k][nq * 4] = v;
        }
        __syncthreads();
#pragma unroll
        for (int k = 0; k < TBK; k++) {
            float a[8], b[8];
            *(float4*)&a[0] = *(const float4*)&As[k][trow];
            *(float4*)&a[4] = *(const float4*)&As[k][trow + 4];
            *(float4*)&b[0] = *(const float4*)&Bs[k][tcol];
            *(float4*)&b[4] = *(const float4*)&Bs[k][tcol + 4];
#pragma unroll
            for (int i = 0; i < 8; i++)
#pragma unroll
                for (int j = 0; j < 8; j++) acc[i][j] = fmaf(a[i], b[j], acc[i][j]);
        }
        __syncthreads();
    }
#pragma unroll
    for (int i = 0; i < 8; i++) {
        int gm = bm + trow + i;
        if (gm < M) {
            float d = g_dinv[gm];                 // prescale epilogue
            __half2 h[4];
            h[0] = __floats2half2_rn(acc[i][0] * d, acc[i][1] * d);
            h[1] = __floats2half2_rn(acc[i][2] * d, acc[i][3] * d);
            h[2] = __floats2half2_rn(acc[i][4] * d, acc[i][5] * d);
            h[3] = __floats2half2_rn(acc[i][6] * d, acc[i][7] * d);
            *(uint4*)(C + (size_t)gm * 128 + tcol) = *(uint4*)h;   // 16B aligned (tcol%8==0)
        }
    }
}

// ---------------- layer-1 gather (fp16 rows, fp32 accum) ----------------
// h1s[n] = fp16(dinv[n]*relu(dinv[n]*(sum xw1s[s] + xw1s[n]) + b1))
__global__ void gather1_kernel(const float* __restrict__ b1) {
    int n = (blockIdx.x * blockDim.x + threadIdx.x) >> 5;
    if (n >= NN) return;
    int lane = threadIdx.x & 31;       // lane covers features [lane*4, lane*4+4)
    int e = g_rowptr[n];
    int end = g_rowptr[n + 1];
    float4 acc = make_float4(0.f, 0.f, 0.f, 0.f);
    for (; e + 1 < end; e += 2) {
        int s0 = g_csr_src[e];
        int s1 = g_csr_src[e + 1];
        uint2 u0 = ((const uint2*)(g_xw1s + (size_t)s0 * F_H1))[lane];
        uint2 u1 = ((const uint2*)(g_xw1s + (size_t)s1 * F_H1))[lane];
        float2 a0 = __half22float2(*(__half2*)&u0.x), b0 = __half22float2(*(__half2*)&u0.y);
        float2 a1 = __half22float2(*(__half2*)&u1.x), b1f = __half22float2(*(__half2*)&u1.y);
        acc.x += a0.x + a1.x;
        acc.y += a0.y + a1.y;
        acc.z += b0.x + b1f.x;
        acc.w += b0.y + b1f.y;
    }
    if (e < end) {
        int s0 = g_csr_src[e];
        uint2 u0 = ((const uint2*)(g_xw1s + (size_t)s0 * F_H1))[lane];
        float2 a0 = __half22float2(*(__half2*)&u0.x), b0 = __half22float2(*(__half2*)&u0.y);
        acc.x += a0.x; acc.y += a0.y; acc.z += b0.x; acc.w += b0.y;
    }
    float d = g_dinv[n];
    uint2 us = ((const uint2*)(g_xw1s + (size_t)n * F_H1))[lane];
    float2 sa = __half22float2(*(__half2*)&us.x), sb = __half22float2(*(__half2*)&us.y);
    float4 bb = ((const float4*)b1)[lane];
    float ox = d * fmaxf(fmaf(acc.x + sa.x, d, bb.x), 0.f);
    float oy = d * fmaxf(fmaf(acc.y + sa.y, d, bb.y), 0.f);
    float oz = d * fmaxf(fmaf(acc.z + sb.x, d, bb.z), 0.f);
    float ow = d * fmaxf(fmaf(acc.w + sb.y, d, bb.w), 0.f);
    __half2 h0 = __floats2half2_rn(ox, oy);
    __half2 h1 = __floats2half2_rn(oz, ow);
    uint2 o;
    o.x = *(unsigned*)&h0;
    o.y = *(unsigned*)&h1;
    ((uint2*)(g_h1s + (size_t)n * F_H1))[lane] = o;
}

// ---------------- layer-2 gather + fused pooling (fp16 rows, fp32 accum+atomics) ----------------
__global__ void gather2_pool_kernel(const int* __restrict__ batch) {
    int n = (blockIdx.x * blockDim.x + threadIdx.x) >> 5;
    if (n >= NN) return;
    int lane = threadIdx.x & 31;
    int e = g_rowptr[n];
    int end = g_rowptr[n + 1];
    float4 acc = make_float4(0.f, 0.f, 0.f, 0.f);
    for (; e + 1 < end; e += 2) {
        int s0 = g_csr_src[e];
        int s1 = g_csr_src[e + 1];
        uint2 u0 = ((const uint2*)(g_h1s + (size_t)s0 * F_H1))[lane];
        uint2 u1 = ((const uint2*)(g_h1s + (size_t)s1 * F_H1))[lane];
        float2 a0 = __half22float2(*(__half2*)&u0.x), b0 = __half22float2(*(__half2*)&u0.y);
        float2 a1 = __half22float2(*(__half2*)&u1.x), b1f = __half22float2(*(__half2*)&u1.y);
        acc.x += a0.x + a1.x;
        acc.y += a0.y + a1.y;
        acc.z += b0.x + b1f.x;
        acc.w += b0.y + b1f.y;
    }
    if (e < end) {
        int s0 = g_csr_src[e];
        uint2 u0 = ((const uint2*)(g_h1s + (size_t)s0 * F_H1))[lane];
        float2 a0 = __half22float2(*(__half2*)&u0.x), b0 = __half22float2(*(__half2*)&u0.y);
        acc.x += a0.x; acc.y += a0.y; acc.z += b0.x; acc.w += b0.y;
    }
    float d = g_dinv[n];
    uint2 us = ((const uint2*)(g_h1s + (size_t)n * F_H1))[lane];
    float2 sa = __half22float2(*(__half2*)&us.x), sb = __half22float2(*(__half2*)&us.y);
    acc.x = (acc.x + sa.x) * d;
    acc.y = (acc.y + sa.y) * d;
    acc.z = (acc.z + sb.x) * d;
    acc.w = (acc.w + sb.y) * d;

    int g = batch[n];
    float* p = g_pool + (size_t)g * F_H1 + lane * 4;
    atomicAdd(p + 0, acc.x);
    atomicAdd(p + 1, acc.y);
    atomicAdd(p + 2, acc.z);
    atomicAdd(p + 3, acc.w);
    if (lane == 0) atomicAdd(&g_cnt[g], 1.0f);
}

// ---------------- heads: tiny @W2+b2 per graph, then group + family logits ----------------
__global__ void logits_kernel(const float* __restrict__ W2, const float* __restrict__ b2,
                              const float* __restrict__ Wg, const float* __restrict__ bg,
                              const float* __restrict__ Wf, const float* __restrict__ bf,
                              float* __restrict__ out) {
    __shared__ float p[F_H1];    // pooled mean, [128]
    __shared__ float h2[F_H2];   // pooled @ W2 + b2, [256]
    int b = blockIdx.x;          // graph
    int t = threadIdx.x;         // 256 threads
    float cnt = fmaxf(g_cnt[b], 1.0f);
    if (t < F_H1) p[t] = g_pool[b * F_H1 + t] / cnt;
    __syncthreads();

    {
        float s = b2[t];
#pragma unroll 8
        for (int k = 0; k < F_H1; k++) s = fmaf(p[k], W2[k * F_H2 + t], s);
        h2[t] = s;
    }
    __syncthreads();

    if (t < N_GROUPS) {
        float s = bg[t];
#pragma unroll 8
        for (int k = 0; k < F_H2; k++) s = fmaf(h2[k], Wg[k * N_GROUPS + t], s);
        out[b * N_GROUPS + t] = s;
    }
    if (t < N_GROUPS * N_FAM) {
        int g = t / N_FAM, f = t - g * N_FAM;
        float s = bf[g * N_FAM + f];
        const float* w = Wf + (size_t)g * F_H2 * N_FAM + f;
#pragma unroll 8
        for (int k = 0; k < F_H2; k++) s = fmaf(h2[k], w[k * N_FAM], s);
        out[NG * N_GROUPS + (size_t)g * NG * N_FAM + b * N_FAM + f] = s;
    }
}

// ---------------- launcher ----------------
extern "C" void kernel_launch(void* const* d_in, const int* in_sizes, int n_in,
                              void* d_out, int out_size) {
    const float* x     = (const float*)d_in[0];
    const int*   ei    = (const int*)d_in[1];     // [2, NE] int32
    const int*   batch = (const int*)d_in[2];
    const float* W1    = (const float*)d_in[3];
    const float* b1    = (const float*)d_in[4];
    const float* W2    = (const float*)d_in[5];
    const float* b2    = (const float*)d_in[6];
    const float* Wg    = (const float*)d_in[7];
    const float* bg    = (const float*)d_in[8];
    const float* Wf    = (const float*)d_in[9];
    const float* bf    = (const float*)d_in[10];
    float* out = (float*)d_out;

    const int* src = ei;
    const int* dst = ei + NE;

    __half* xw1s;
    cudaGetSymbolAddress((void**)&xw1s, g_xw1s);

    // degree histogram + scan(+dinv) + CSR fill
    zero_kernel<<<(NN + 255) / 256, 256>>>();
    hist_kernel<<<(NE + 255) / 256, 256>>>(dst);
    scan_block_kernel<<<NBLK_SCAN, SCAN_BLK>>>();
    scan_sums_kernel<<<1, 512>>>();
    scan_add_kernel<<<(NN + 255) / 256, 256>>>();
    csr_fill_kernel<<<(NE + 255) / 256, 256>>>(src, dst);

    // layer 1: xw1s = fp16(dinv * (x @ W1)); gather -> h1s = fp16(dinv*relu(agg1))
    gemm1_kernel<<<(NN + TBM - 1) / TBM, 256>>>(x, W1, xw1s, NN);
    gather1_kernel<<<(NN * 32 + 255) / 256, 256>>>(b1);

    // layer 2 (reassociated): pool(A_hat * relu(agg1)); @W2 deferred to heads
    gather2_pool_kernel<<<(NN * 32 + 255) / 256, 256>>>(batch);

    // heads: per-graph @W2+b2 then logits
    logits_kernel<<<NG, F_H2>>>(W2, b2, Wg, bg, Wf, bf, out);
}

// round 12
// speedup vs baseline: 7.2714x; 1.1113x over previous
#include <cuda_runtime.h>
#include <cuda_fp16.h>

#define NN 100000
#define NE 1600000
#define NG 512
#define F_IN 128
#define F_H1 128
#define F_H2 256
#define N_GROUPS 16
#define N_FAM 10

#define SCAN_BLK 256
#define NBLK_SCAN ((NN + SCAN_BLK - 1) / SCAN_BLK)   // 391

// ---------------- scratch (device globals: allocation-guard-safe) ----------------
__device__ __half g_xw1s[(size_t)NN * F_H1]; // dinv * (x @ W1), fp16 (25.6 MB, L2-resident)
__device__ __half g_h1s[(size_t)NN * F_H1];  // dinv * relu(agg1), fp16 (25.6 MB, L2-resident)
__device__ __half g_w1t[F_H1 * F_IN];        // W1 transposed [n][k], fp16
__device__ float g_dinv[NN];                 // rsqrt(deg+1)
__device__ int   g_deg[NN];                  // in-degree histogram
__device__ int   g_rowptr[NN + 1];           // CSR row pointers (by dst)
__device__ int   g_fill[NN];                 // running fill cursors
__device__ int   g_blocksum[NBLK_SCAN + 1];  // scan partials
__device__ int   g_csr_src[NE];              // src ids, dst-ordered
__device__ float g_pool[NG * F_H1];          // pooled sums [512,128] (fp32)
__device__ float g_cnt[NG];                  // segment counts

__device__ __forceinline__ unsigned smem_u32(const void* p) {
    unsigned a;
    asm("{.reg .u64 t; cvta.to.shared.u64 t, %1; cvt.u32.u64 %0, t;}" : "=r"(a) : "l"(p));
    return a;
}

// ---------------- zero + degree histogram ----------------
// NOTE: must cover NN threads (g_deg) — replay idempotence.
__global__ void zero_kernel() {
    int i = blockIdx.x * blockDim.x + threadIdx.x;
    if (i < NN) g_deg[i] = 0;
    if (i < NG * F_H1) g_pool[i] = 0.f;
    if (i < NG) g_cnt[i] = 0.f;
}

__global__ void hist_kernel(const int* __restrict__ dst) {
    int e = blockIdx.x * blockDim.x + threadIdx.x;
    if (e < NE) atomicAdd(&g_deg[dst[e]], 1);
}

// ---------------- exclusive scan of g_deg -> g_rowptr (dinv fused in) ----------------
__global__ void scan_block_kernel() {
    __shared__ int s[SCAN_BLK];
    int tid = threadIdx.x;
    int i = blockIdx.x * SCAN_BLK + tid;
    int v = (i < NN) ? g_deg[i] : 0;
    if (i < NN) g_dinv[i] = rsqrtf((float)v + 1.0f);   // fused dinv
    s[tid] = v;
    __syncthreads();
#pragma unroll
    for (int off = 1; off < SCAN_BLK; off <<= 1) {
        int t = (tid >= off) ? s[tid - off] : 0;
        __syncthreads();
        s[tid] += t;
        __syncthreads();
    }
    if (i < NN) g_rowptr[i] = s[tid] - v;      // exclusive within block
    if (tid == SCAN_BLK - 1) g_blocksum[blockIdx.x] = s[tid];
}

__global__ void scan_sums_kernel() {
    __shared__ int s[512];
    int tid = threadIdx.x;                      // 512 threads
    int v = (tid < NBLK_SCAN) ? g_blocksum[tid] : 0;
    s[tid] = v;
    __syncthreads();
#pragma unroll
    for (int off = 1; off < 512; off <<= 1) {
        int t = (tid >= off) ? s[tid - off] : 0;
        __syncthreads();
        s[tid] += t;
        __syncthreads();
    }
    if (tid < NBLK_SCAN) g_blocksum[tid] = s[tid] - v;   // exclusive
}

__global__ void scan_add_kernel() {
    int i = blockIdx.x * blockDim.x + threadIdx.x;
    if (i < NN) {
        int r = g_rowptr[i] + g_blocksum[i / SCAN_BLK];
        g_rowptr[i] = r;
        g_fill[i] = r;
    }
    if (i == 0) g_rowptr[NN] = NE;
}

// ---------------- CSR fill (src ids only) ----------------
__global__ void csr_fill_kernel(const int* __restrict__ src, const int* __restrict__ dst) {
    int e = blockIdx.x * blockDim.x + threadIdx.x;
    if (e >= NE) return;
    int pos = atomicAdd(&g_fill[dst[e]], 1);
    g_csr_src[pos] = src[e];
}

// ---------------- W1 transpose + fp16 convert: W1T[n][k] = W1[k][n] ----------------
__global__ void w1t_kernel(const float* __restrict__ W1) {
    int i = blockIdx.x * blockDim.x + threadIdx.x;   // 16384
    int n = i >> 7, k = i & 127;
    g_w1t[n * 128 + k] = __float2half(W1[k * 128 + n]);
}

// ---------------- GEMM1 (tensor cores): xw1s = fp16(dinv * (x @ W1)) ----------------
// 128x128 tile, whole K=128 in smem, 512 threads = 4x4 warps, warp tile 32x32.
// mma.sync.m16n8k16 f16*f16 -> f32 accum; A row-major, B col-major (W1T k-contiguous).
#define AS_STRIDE 136   // halves; 272B row stride -> conflict-free ldmatrix
__global__ __launch_bounds__(512) void gemm1_mma_kernel(const float* __restrict__ A,
                                                        __half* __restrict__ C, int M) {
    extern __shared__ char smem_raw[];
    __half* As = (__half*)smem_raw;                      // [128][AS_STRIDE]
    __half* Bs = As + 128 * AS_STRIDE;                   // [128][AS_STRIDE] (n-major, k contiguous)
    int tid = threadIdx.x;
    int bm = blockIdx.x * 128;

    // A tile: 128 rows x 128 k, fp32 -> fp16 on the fly
    for (int idx = tid; idx < 128 * 32; idx += 512) {
        int m = idx >> 5, q = idx & 31;
        int gm = bm + m;
        float4 v = (gm < M) ? ((const float4*)(A + (size_t)gm * 128))[q]
                            : make_float4(0.f, 0.f, 0.f, 0.f);
        __half2 h0 = __floats2half2_rn(v.x, v.y);
        __half2 h1 = __floats2half2_rn(v.z, v.w);
        *(__half2*)&As[m * AS_STRIDE + q * 4]     = h0;
        *(__half2*)&As[m * AS_STRIDE + q * 4 + 2] = h1;
    }
    // B tile: W1T [n][k] fp16, straight copy
    for (int idx = tid; idx < 2048; idx += 512) {
        int n = idx >> 4, q = idx & 15;
        *(uint4*)&Bs[n * AS_STRIDE + q * 8] = ((const uint4*)(g_w1t + n * 128))[q];
    }
    __syncthreads();

    int lane = tid & 31, warp = tid >> 5;
    int wm = (warp >> 2) * 32;
    int wn = (warp & 3) * 32;
    float acc[2][4][4];
#pragma unroll
    for (int i = 0; i < 2; i++)
#pragma unroll
        for (int j = 0; j < 4; j++)
#pragma unroll
            for (int r = 0; r < 4; r++) acc[i][j][r] = 0.f;

    int lr = (lane & 7) + ((lane >> 3) & 1) * 8;   // A: row within 16
    int lk = ((lane >> 4) & 1) * 8;                // A: k-half select
    int l16 = lane & 15;
    int brow = l16 & 7;                            // B: n-row within 8
    int bk = ((l16 >> 3) & 1) * 8;                 // B: k-half select

#pragma unroll
    for (int k0 = 0; k0 < 128; k0 += 16) {
        unsigned a[2][4];
#pragma unroll
        for (int fi = 0; fi < 2; fi++) {
            unsigned addr = smem_u32(&As[(wm + fi * 16 + lr) * AS_STRIDE + k0 + lk]);
            asm volatile("ldmatrix.sync.aligned.m8n8.x4.shared.b16 {%0,%1,%2,%3}, [%4];"
                         : "=r"(a[fi][0]), "=r"(a[fi][1]), "=r"(a[fi][2]), "=r"(a[fi][3])
                         : "r"(addr));
        }
        unsigned b[4][2];
#pragma unroll
        for (int fj = 0; fj < 4; fj++) {
            unsigned addr = smem_u32(&Bs[(wn + fj * 8 + brow) * AS_STRIDE + k0 + bk]);
            asm volatile("ldmatrix.sync.aligned.m8n8.x2.shared.b16 {%0,%1}, [%2];"
                         : "=r"(b[fj][0]), "=r"(b[fj][1])
                         : "r"(addr));
        }
#pragma unroll
        for (int fi = 0; fi < 2; fi++)
#pragma unroll
            for (int fj = 0; fj < 4; fj++) {
                asm volatile(
                    "mma.sync.aligned.m16n8k16.row.col.f32.f16.f16.f32 "
                    "{%0,%1,%2,%3}, {%4,%5,%6,%7}, {%8,%9}, {%0,%1,%2,%3};"
                    : "+f"(acc[fi][fj][0]), "+f"(acc[fi][fj][1]),
                      "+f"(acc[fi][fj][2]), "+f"(acc[fi][fj][3])
                    : "r"(a[fi][0]), "r"(a[fi][1]), "r"(a[fi][2]), "r"(a[fi][3]),
                      "r"(b[fj][0]), "r"(b[fj][1]));
            }
    }

    // epilogue: scale by dinv[row], convert to fp16, store pairs
#pragma unroll
    for (int fi = 0; fi < 2; fi++) {
        int r0 = bm + wm + fi * 16 + (lane >> 2);
        int r1 = r0 + 8;
        float d0 = (r0 < M) ? g_dinv[r0] : 0.f;
        float d1 = (r1 < M) ? g_dinv[r1] : 0.f;
#pragma unroll
        for (int fj = 0; fj < 4; fj++) {
            int c = wn + fj * 8 + (lane & 3) * 2;
            if (r0 < M)
                *(__half2*)(C + (size_t)r0 * 128 + c) =
                    __floats2half2_rn(acc[fi][fj][0] * d0, acc[fi][fj][1] * d0);
            if (r1 < M)
                *(__half2*)(C + (size_t)r1 * 128 + c) =
                    __floats2half2_rn(acc[fi][fj][2] * d1, acc[fi][fj][3] * d1);
        }
    }
}

// ---------------- layer-1 gather (fp16 rows, fp32 accum) ----------------
// h1s[n] = fp16(dinv[n]*relu(dinv[n]*(sum xw1s[s] + xw1s[n]) + b1))
__global__ void gather1_kernel(const float* __restrict__ b1) {
    int n = (blockIdx.x * blockDim.x + threadIdx.x) >> 5;
    if (n >= NN) return;
    int lane = threadIdx.x & 31;       // lane covers features [lane*4, lane*4+4)
    int e = g_rowptr[n];
    int end = g_rowptr[n + 1];
    float4 acc = make_float4(0.f, 0.f, 0.f, 0.f);
    for (; e + 1 < end; e += 2) {
        int s0 = g_csr_src[e];
        int s1 = g_csr_src[e + 1];
        uint2 u0 = ((const uint2*)(g_xw1s + (size_t)s0 * F_H1))[lane];
        uint2 u1 = ((const uint2*)(g_xw1s + (size_t)s1 * F_H1))[lane];
        float2 a0 = __half22float2(*(__half2*)&u0.x), b0 = __half22float2(*(__half2*)&u0.y);
        float2 a1 = __half22float2(*(__half2*)&u1.x), b1f = __half22float2(*(__half2*)&u1.y);
        acc.x += a0.x + a1.x;
        acc.y += a0.y + a1.y;
        acc.z += b0.x + b1f.x;
        acc.w += b0.y + b1f.y;
    }
    if (e < end) {
        int s0 = g_csr_src[e];
        uint2 u0 = ((const uint2*)(g_xw1s + (size_t)s0 * F_H1))[lane];
        float2 a0 = __half22float2(*(__half2*)&u0.x), b0 = __half22float2(*(__half2*)&u0.y);
        acc.x += a0.x; acc.y += a0.y; acc.z += b0.x; acc.w += b0.y;
    }
    float d = g_dinv[n];
    uint2 us = ((const uint2*)(g_xw1s + (size_t)n * F_H1))[lane];
    float2 sa = __half22float2(*(__half2*)&us.x), sb = __half22float2(*(__half2*)&us.y);
    float4 bb = ((const float4*)b1)[lane];
    float ox = d * fmaxf(fmaf(acc.x + sa.x, d, bb.x), 0.f);
    float oy = d * fmaxf(fmaf(acc.y + sa.y, d, bb.y), 0.f);
    float oz = d * fmaxf(fmaf(acc.z + sb.x, d, bb.z), 0.f);
    float ow = d * fmaxf(fmaf(acc.w + sb.y, d, bb.w), 0.f);
    __half2 h0 = __floats2half2_rn(ox, oy);
    __half2 h1 = __floats2half2_rn(oz, ow);
    uint2 o;
    o.x = *(unsigned*)&h0;
    o.y = *(unsigned*)&h1;
    ((uint2*)(g_h1s + (size_t)n * F_H1))[lane] = o;
}

// ---------------- layer-2 gather + fused pooling (fp16 rows, fp32 accum+atomics) ----------------
__global__ void gather2_pool_kernel(const int* __restrict__ batch) {
    int n = (blockIdx.x * blockDim.x + threadIdx.x) >> 5;
    if (n >= NN) return;
    int lane = threadIdx.x & 31;
    int e = g_rowptr[n];
    int end = g_rowptr[n + 1];
    float4 acc = make_float4(0.f, 0.f, 0.f, 0.f);
    for (; e + 1 < end; e += 2) {
        int s0 = g_csr_src[e];
        int s1 = g_csr_src[e + 1];
        uint2 u0 = ((const uint2*)(g_h1s + (size_t)s0 * F_H1))[lane];
        uint2 u1 = ((const uint2*)(g_h1s + (size_t)s1 * F_H1))[lane];
        float2 a0 = __half22float2(*(__half2*)&u0.x), b0 = __half22float2(*(__half2*)&u0.y);
        float2 a1 = __half22float2(*(__half2*)&u1.x), b1f = __half22float2(*(__half2*)&u1.y);
        acc.x += a0.x + a1.x;
        acc.y += a0.y + a1.y;
        acc.z += b0.x + b1f.x;
        acc.w += b0.y + b1f.y;
    }
    if (e < end) {
        int s0 = g_csr_src[e];
        uint2 u0 = ((const uint2*)(g_h1s + (size_t)s0 * F_H1))[lane];
        float2 a0 = __half22float2(*(__half2*)&u0.x), b0 = __half22float2(*(__half2*)&u0.y);
        acc.x += a0.x; acc.y += a0.y; acc.z += b0.x; acc.w += b0.y;
    }
    float d = g_dinv[n];
    uint2 us = ((const uint2*)(g_h1s + (size_t)n * F_H1))[lane];
    float2 sa = __half22float2(*(__half2*)&us.x), sb = __half22float2(*(__half2*)&us.y);
    acc.x = (acc.x + sa.x) * d;
    acc.y = (acc.y + sa.y) * d;
    acc.z = (acc.z + sb.x) * d;
    acc.w = (acc.w + sb.y) * d;

    int g = batch[n];
    float* p = g_pool + (size_t)g * F_H1 + lane * 4;
    atomicAdd(p + 0, acc.x);
    atomicAdd(p + 1, acc.y);
    atomicAdd(p + 2, acc.z);
    atomicAdd(p + 3, acc.w);
    if (lane == 0) atomicAdd(&g_cnt[g], 1.0f);
}

// ---------------- heads: tiny @W2+b2 per graph, then group + family logits ----------------
__global__ void logits_kernel(const float* __restrict__ W2, const float* __restrict__ b2,
                              const float* __restrict__ Wg, const float* __restrict__ bg,
                              const float* __restrict__ Wf, const float* __restrict__ bf,
                              float* __restrict__ out) {
    __shared__ float p[F_H1];    // pooled mean, [128]
    __shared__ float h2[F_H2];   // pooled @ W2 + b2, [256]
    int b = blockIdx.x;          // graph
    int t = threadIdx.x;         // 256 threads
    float cnt = fmaxf(g_cnt[b], 1.0f);
    if (t < F_H1) p[t] = g_pool[b * F_H1 + t] / cnt;
    __syncthreads();

    {
        float s = b2[t];
#pragma unroll 8
        for (int k = 0; k < F_H1; k++) s = fmaf(p[k], W2[k * F_H2 + t], s);
        h2[t] = s;
    }
    __syncthreads();

    if (t < N_GROUPS) {
        float s = bg[t];
#pragma unroll 8
        for (int k = 0; k < F_H2; k++) s = fmaf(h2[k], Wg[k * N_GROUPS + t], s);
        out[b * N_GROUPS + t] = s;
    }
    if (t < N_GROUPS * N_FAM) {
        int g = t / N_FAM, f = t - g * N_FAM;
        float s = bf[g * N_FAM + f];
        const float* w = Wf + (size_t)g * F_H2 * N_FAM + f;
#pragma unroll 8
        for (int k = 0; k < F_H2; k++) s = fmaf(h2[k], w[k * N_FAM], s);
        out[NG * N_GROUPS + (size_t)g * NG * N_FAM + b * N_FAM + f] = s;
    }
}

// ---------------- launcher ----------------
extern "C" void kernel_launch(void* const* d_in, const int* in_sizes, int n_in,
                              void* d_out, int out_size) {
    const float* x     = (const float*)d_in[0];
    const int*   ei    = (const int*)d_in[1];     // [2, NE] int32
    const int*   batch = (const int*)d_in[2];
    const float* W1    = (const float*)d_in[3];
    const float* b1    = (const float*)d_in[4];
    const float* W2    = (const float*)d_in[5];
    const float* b2    = (const float*)d_in[6];
    const float* Wg    = (const float*)d_in[7];
    const float* bg    = (const float*)d_in[8];
    const float* Wf    = (const float*)d_in[9];
    const float* bf    = (const float*)d_in[10];
    float* out = (float*)d_out;

    const int* src = ei;
    const int* dst = ei + NE;

    __half* xw1s;
    cudaGetSymbolAddress((void**)&xw1s, g_xw1s);

    const int GEMM_SMEM = 2 * 128 * AS_STRIDE * 2;   // 69632 B
    cudaFuncSetAttribute(gemm1_mma_kernel, cudaFuncAttributeMaxDynamicSharedMemorySize,
                         GEMM_SMEM);

    // degree histogram + scan(+dinv) + CSR fill
    zero_kernel<<<(NN + 255) / 256, 256>>>();
    hist_kernel<<<(NE + 255) / 256, 256>>>(dst);
    scan_block_kernel<<<NBLK_SCAN, SCAN_BLK>>>();
    scan_sums_kernel<<<1, 512>>>();
    scan_add_kernel<<<(NN + 255) / 256, 256>>>();
    csr_fill_kernel<<<(NE + 255) / 256, 256>>>(src, dst);

    // layer 1: W1 transpose, tensor-core GEMM, gather
    w1t_kernel<<<(F_H1 * F_IN + 255) / 256, 256>>>(W1);
    gemm1_mma_kernel<<<(NN + 127) / 128, 512, GEMM_SMEM>>>(x, xw1s, NN);
    gather1_kernel<<<(NN * 32 + 255) / 256, 256>>>(b1);

    // layer 2 (reassociated): pool(A_hat * relu(agg1)); @W2 deferred to heads
    gather2_pool_kernel<<<(NN * 32 + 255) / 256, 256>>>(batch);

    // heads: per-graph @W2+b2 then logits
    logits_kernel<<<NG, F_H2>>>(W2, b2, Wg, bg, Wf, bf, out);
}